// round 6
// baseline (speedup 1.0000x reference)
#include <cuda_runtime.h>

// SliceLSTM persistent kernel, round 6: barrier-free dataflow.
// B=64, T=512, S=4, DIN=64, H=128, HTOT=512.
// 128 CTAs x 256 threads, all co-resident (116KB smem => 1 CTA/SM).
// Per step: P1 stage-1 GEMM -> actflag; P2 connector GEMM -> pcnt counter;
// P3 reduce+cell update -> hcnt counter. No global barriers; parity
// double-buffered h/act/partials; all cross-CTA data via L2 (.cg).

#define NCTA 128
#define NTHR 256
#define LD1 193
#define LD2 65

#define OFF_W1 0        // 192 x 16
#define OFF_B1 3072     // 16
#define OFF_W2 3088     // 64 x 128
#define OFF_A1 11280    // 64 x 193  (k<64: x, k>=64: h)
#define OFF_A2 23632    // 64 x 65
#define OFF_SC 27792    // 512 u64 scratch
#define SMEM_BYTES 118784

__device__ float g_hbuf[2][64 * 512];            // [parity][b][c]
__device__ float g_act[2][4 * 64 * 512];         // [parity][gate][b][c]
__device__ float g_part[2][NCTA * 64 * 128];     // [parity][blk][b][cl]
__device__ unsigned g_actflag[NCTA * 8];         // stride 8 (32B)
__device__ unsigned g_pcnt[4 * 64];              // stride 64 (256B)
__device__ unsigned g_hcnt[4 * 64];

static __device__ __forceinline__ unsigned long long pk2(float v) {
    unsigned long long r;
    asm("mov.b64 %0, {%1, %1};" : "=l"(r) : "f"(v));
    return r;
}
static __device__ __forceinline__ void unp2(unsigned long long v, float& lo, float& hi) {
    asm("mov.b64 {%0, %1}, %2;" : "=f"(lo), "=f"(hi) : "l"(v));
}
static __device__ __forceinline__ void fma2(unsigned long long& d,
                                            unsigned long long a, unsigned long long b) {
    asm("fma.rn.f32x2 %0, %1, %2, %0;" : "+l"(d) : "l"(a), "l"(b));
}
static __device__ __forceinline__ float sigf(float x)  { return 1.0f / (1.0f + __expf(-x)); }
static __device__ __forceinline__ float tanhe(float x) {
    float e = __expf(2.0f * x);
    return 1.0f - 2.0f / (e + 1.0f);
}
static __device__ __forceinline__ unsigned ldacq(const unsigned* p) {
    unsigned v;
    asm volatile("ld.acquire.gpu.global.u32 %0, [%1];" : "=r"(v) : "l"(p) : "memory");
    return v;
}
static __device__ __forceinline__ void strel(unsigned* p, unsigned v) {
    asm volatile("st.release.gpu.global.u32 [%0], %1;" :: "l"(p), "r"(v) : "memory");
}
static __device__ __forceinline__ void redrel(unsigned* p) {
    asm volatile("red.release.gpu.global.add.u32 [%0], 1;" :: "l"(p) : "memory");
}

__global__ void zero_kernel() {
    int i = blockIdx.x * blockDim.x + threadIdx.x;
    int n = blockDim.x * gridDim.x;
    for (int j = i; j < 64 * 512; j += n) g_hbuf[0][j] = 0.0f;
    for (int j = i; j < NCTA * 8; j += n) g_actflag[j] = 0u;
    for (int j = i; j < 4 * 64; j += n) { g_pcnt[j] = 0u; g_hcnt[j] = 0u; }
}

__global__ void __launch_bounds__(NTHR, 1)
slstm_kernel(const float* __restrict__ x,       // (64, 512, 256)
             const float* __restrict__ Ws,      // (4, 64, 512)
             const float* __restrict__ Us,      // (4, 128, 512)
             const float* __restrict__ biases,  // (4, 512)
             const float* __restrict__ Wc,      // (512, 2048)
             const float* __restrict__ bc,      // (2048,)
             float* __restrict__ out)           // hseq | h_t | c_t
{
    extern __shared__ float sm[];
    float* sW1 = sm + OFF_W1;
    float* sB1 = sm + OFF_B1;
    float* sW2 = sm + OFF_W2;
    float* sA1 = sm + OFF_A1;
    float* sA2 = sm + OFF_A2;
    unsigned long long* sSc = reinterpret_cast<unsigned long long*>(sm + OFF_SC);

    const int tid = threadIdx.x;
    const int cta = blockIdx.x;

    // P1 role: slice s1, 16 stage-1 cols at u0 (single gate)
    const int s1    = cta >> 5;
    const int u0    = (cta & 31) * 16;
    const int gate1 = u0 >> 7;
    const int col0  = s1 * 128 + (u0 & 127);
    const int p1bg  = tid & 31;          // 2-batch group
    const int p1cg  = (tid >> 5) & 1;    // 8-col half
    const int p1ks  = (tid >> 6) & 1;    // K half

    // P2 role: gate g2, col-tile ct2 (128 cols), K-chunk kc2 (64 rows)
    const int g2  = cta >> 5;
    const int ct2 = (cta >> 3) & 3;
    const int kc2 = cta & 7;
    const int c20 = ct2 * 128;
    const int k20 = kc2 * 64;
    const int p2bg = tid & 15;           // 4-batch group
    const int p2cg = tid >> 4;           // 16-col group (tid<128)
    // producers of act[g2][:, k20..k20+64): 4 P1 CTAs
    const int prod = ((kc2 >> 1) << 5) | (g2 << 3) | ((kc2 & 1) << 2);

    // P3 role: CTA owns col-tile ct3 (128 cols) x 2 batches (b0, b0+1)
    const int ct3 = cta & 3;
    const int b0  = (cta >> 2) * 2;
    const int boff = (tid >> 5) & 1;     // tid<64: which of the 2 batches
    const int c4   = (tid & 31) * 4;     // 4 cols within the tile

    // ---- persistent weights ----
    for (int i = tid; i < 192 * 16; i += NTHR) {
        int k = i >> 4, c = i & 15;
        sW1[i] = (k < 64) ? Ws[s1 * (64 * 512) + k * 512 + u0 + c]
                          : Us[s1 * (128 * 512) + (k - 64) * 512 + u0 + c];
    }
    if (tid < 16) sB1[tid] = biases[s1 * 512 + u0 + tid];
    for (int i = tid; i < 64 * 128; i += NTHR) {
        int k = i >> 7, c = i & 127;
        sW2[k * 128 + c] = Wc[(k20 + k) * 2048 + g2 * 512 + c20 + c];
    }

    // P3 biases + state
    float4 bi = {0,0,0,0}, bf = {0,0,0,0}, bg4 = {0,0,0,0}, bo = {0,0,0,0};
    float4 creg = {0,0,0,0}, hlast = {0,0,0,0};
    if (tid < 64) {
        const int cc = ct3 * 128 + c4;
        bi  = *reinterpret_cast<const float4*>(&bc[cc]);
        bf  = *reinterpret_cast<const float4*>(&bc[512 + cc]);
        bg4 = *reinterpret_cast<const float4*>(&bc[1024 + cc]);
        bo  = *reinterpret_cast<const float4*>(&bc[1536 + cc]);
    }
    // stage x(t=0): 256 (b,q) pairs, 16 floats each
    for (int i = tid; i < 256; i += NTHR) {
        int b = i & 63, q = i >> 6;
        const float4* src = reinterpret_cast<const float4*>(
            &x[b * (512 * 256) + s1 * 64 + q * 16]);
        float* dst = &sA1[b * LD1 + q * 16];
        #pragma unroll
        for (int j = 0; j < 4; ++j) {
            float4 v = __ldg(src + j);
            dst[j * 4 + 0] = v.x; dst[j * 4 + 1] = v.y;
            dst[j * 4 + 2] = v.z; dst[j * 4 + 3] = v.w;
        }
    }

    for (int t = 0; t < 512; ++t) {
        const int p  = t & 1;
        const int pn = p ^ 1;

        // ================= P1: wait h, stage h, block-diag GEMM =================
        if (tid == 0) {
            const unsigned need = 32u * (unsigned)t;
            while (ldacq(&g_hcnt[s1 * 64]) < need) {}
        }
        __syncthreads();
        {
            const float* hb = g_hbuf[p];
            for (int i = tid; i < 256; i += NTHR) {
                int b = i & 63, q = i >> 6;
                const float4* src = reinterpret_cast<const float4*>(
                    &hb[b * 512 + s1 * 128 + q * 32]);
                float* dst = &sA1[b * LD1 + 64 + q * 32];
                #pragma unroll
                for (int j = 0; j < 8; ++j) {
                    float4 v = __ldcg(src + j);
                    dst[j * 4 + 0] = v.x; dst[j * 4 + 1] = v.y;
                    dst[j * 4 + 2] = v.z; dst[j * 4 + 3] = v.w;
                }
            }
        }
        __syncthreads();
        unsigned long long acc1[2][4];
        if (tid < 128) {
            const int b = p1bg * 2;
            const float* a0p = sA1 + (b + 0) * LD1;
            const float* a1p = sA1 + (b + 1) * LD1;
            const float* wp  = sW1 + p1cg * 8;
            #pragma unroll
            for (int i = 0; i < 2; ++i)
                #pragma unroll
                for (int j = 0; j < 4; ++j) acc1[i][j] = 0ULL;
            const int kbeg = p1ks * 96;
            #pragma unroll 4
            for (int k = kbeg; k < kbeg + 96; ++k) {
                const ulonglong2 wA = *reinterpret_cast<const ulonglong2*>(wp + k * 16);
                const ulonglong2 wB = *reinterpret_cast<const ulonglong2*>(wp + k * 16 + 4);
                const unsigned long long a0 = pk2(a0p[k]);
                const unsigned long long a1 = pk2(a1p[k]);
                fma2(acc1[0][0], a0, wA.x); fma2(acc1[0][1], a0, wA.y);
                fma2(acc1[0][2], a0, wB.x); fma2(acc1[0][3], a0, wB.y);
                fma2(acc1[1][0], a1, wA.x); fma2(acc1[1][1], a1, wA.y);
                fma2(acc1[1][2], a1, wB.x); fma2(acc1[1][3], a1, wB.y);
            }
            if (p1ks == 1) {
                const int th = tid - 64;
                #pragma unroll
                for (int i = 0; i < 2; ++i)
                    #pragma unroll
                    for (int j = 0; j < 4; ++j)
                        sSc[(i * 4 + j) * 64 + th] = acc1[i][j];
            }
        }
        __syncthreads();
        if (tid < 64) {
            const int b = p1bg * 2;
            float* actp = g_act[p];
            #pragma unroll
            for (int i = 0; i < 2; ++i) {
                float v[8];
                #pragma unroll
                for (int j = 0; j < 4; ++j) {
                    float lo, hi, plo, phi;
                    unp2(acc1[i][j], lo, hi);
                    unp2(sSc[(i * 4 + j) * 64 + tid], plo, phi);
                    v[2 * j]     = lo + plo + sB1[p1cg * 8 + 2 * j];
                    v[2 * j + 1] = hi + phi + sB1[p1cg * 8 + 2 * j + 1];
                }
                if (gate1 == 2) {
                    #pragma unroll
                    for (int j = 0; j < 8; ++j) v[j] = tanhe(v[j]);
                } else {
                    #pragma unroll
                    for (int j = 0; j < 8; ++j) v[j] = sigf(v[j]);
                }
                float* dst = &actp[gate1 * 32768 + (b + i) * 512 + col0 + p1cg * 8];
                __stcg(reinterpret_cast<float4*>(dst),
                       make_float4(v[0], v[1], v[2], v[3]));
                __stcg(reinterpret_cast<float4*>(dst + 4),
                       make_float4(v[4], v[5], v[6], v[7]));
            }
        }
        __syncthreads();
        if (tid == 0) {
            __threadfence();
            strel(&g_actflag[cta * 8], (unsigned)(t + 1));
        }

        // ================= P2: wait producers, stage act, connector GEMM =================
        if (tid < 4) {
            const unsigned need = (unsigned)(t + 1);
            const unsigned* f = &g_actflag[(prod + tid) * 8];
            while (ldacq(f) < need) {}
        }
        __syncthreads();
        {
            const float* ab = g_act[p] + g2 * 32768;
            for (int i = tid; i < 256; i += NTHR) {
                int b = i & 63, q = i >> 6;
                const float4* src = reinterpret_cast<const float4*>(
                    &ab[b * 512 + k20 + q * 16]);
                float* dst = &sA2[b * LD2 + q * 16];
                #pragma unroll
                for (int j = 0; j < 4; ++j) {
                    float4 v = __ldcg(src + j);
                    dst[j * 4 + 0] = v.x; dst[j * 4 + 1] = v.y;
                    dst[j * 4 + 2] = v.z; dst[j * 4 + 3] = v.w;
                }
            }
        }
        __syncthreads();
        if (tid < 128) {
            const int b = p2bg * 4;
            unsigned long long acc[4][8];
            #pragma unroll
            for (int i = 0; i < 4; ++i)
                #pragma unroll
                for (int j = 0; j < 8; ++j) acc[i][j] = 0ULL;
            const float* wbase = sW2 + p2cg * 16;
            #pragma unroll 4
            for (int k = 0; k < 64; ++k) {
                const float* wr = wbase + k * 128;
                const ulonglong2 wA = *reinterpret_cast<const ulonglong2*>(wr);
                const ulonglong2 wB = *reinterpret_cast<const ulonglong2*>(wr + 4);
                const ulonglong2 wC = *reinterpret_cast<const ulonglong2*>(wr + 8);
                const ulonglong2 wD = *reinterpret_cast<const ulonglong2*>(wr + 12);
                #pragma unroll
                for (int i = 0; i < 4; ++i) {
                    const unsigned long long a = pk2(sA2[(b + i) * LD2 + k]);
                    fma2(acc[i][0], a, wA.x); fma2(acc[i][1], a, wA.y);
                    fma2(acc[i][2], a, wB.x); fma2(acc[i][3], a, wB.y);
                    fma2(acc[i][4], a, wC.x); fma2(acc[i][5], a, wC.y);
                    fma2(acc[i][6], a, wD.x); fma2(acc[i][7], a, wD.y);
                }
            }
            float* pp = g_part[p] + cta * 8192 + p2cg * 16;
            #pragma unroll
            for (int i = 0; i < 4; ++i) {
                float q0,q1,q2,q3,q4,q5,q6,q7,q8,q9,qa,qb,qc,qd,qe,qf;
                unp2(acc[i][0], q0, q1); unp2(acc[i][1], q2, q3);
                unp2(acc[i][2], q4, q5); unp2(acc[i][3], q6, q7);
                unp2(acc[i][4], q8, q9); unp2(acc[i][5], qa, qb);
                unp2(acc[i][6], qc, qd); unp2(acc[i][7], qe, qf);
                float4* d = reinterpret_cast<float4*>(pp + (b + i) * 128);
                __stcg(d + 0, make_float4(q0, q1, q2, q3));
                __stcg(d + 1, make_float4(q4, q5, q6, q7));
                __stcg(d + 2, make_float4(q8, q9, qa, qb));
                __stcg(d + 3, make_float4(qc, qd, qe, qf));
            }
        } else if (t + 1 < 512) {
            // x prefetch for t+1 during P2 GEMM
            for (int i = tid - 128; i < 256; i += 128) {
                int b = i & 63, q = i >> 6;
                const float4* src = reinterpret_cast<const float4*>(
                    &x[b * (512 * 256) + (t + 1) * 256 + s1 * 64 + q * 16]);
                float* dst = &sA1[b * LD1 + q * 16];
                #pragma unroll
                for (int j = 0; j < 4; ++j) {
                    float4 v = __ldg(src + j);
                    dst[j * 4 + 0] = v.x; dst[j * 4 + 1] = v.y;
                    dst[j * 4 + 2] = v.z; dst[j * 4 + 3] = v.w;
                }
            }
        }
        __syncthreads();
        if (tid == 0) {
            __threadfence();
            redrel(&g_pcnt[ct2 * 64]);
            const unsigned need = 32u * (unsigned)(t + 1);
            while (ldacq(&g_pcnt[ct3 * 64]) < need) {}
        }
        __syncthreads();

        // ================= P3: gather partials + cell update =================
        if (tid < 64) {
            const int bb = b0 + boff;
            float4 ai = {0,0,0,0}, af = {0,0,0,0}, ag = {0,0,0,0}, ao = {0,0,0,0};
            const float* pb = g_part[p] + bb * 128 + c4;
            #pragma unroll
            for (int kc = 0; kc < 8; ++kc) {
                float4 v;
                v = __ldcg(reinterpret_cast<const float4*>(pb + (0 * 32 + ct3 * 8 + kc) * 8192));
                ai.x += v.x; ai.y += v.y; ai.z += v.z; ai.w += v.w;
                v = __ldcg(reinterpret_cast<const float4*>(pb + (1 * 32 + ct3 * 8 + kc) * 8192));
                af.x += v.x; af.y += v.y; af.z += v.z; af.w += v.w;
                v = __ldcg(reinterpret_cast<const float4*>(pb + (2 * 32 + ct3 * 8 + kc) * 8192));
                ag.x += v.x; ag.y += v.y; ag.z += v.z; ag.w += v.w;
                v = __ldcg(reinterpret_cast<const float4*>(pb + (3 * 32 + ct3 * 8 + kc) * 8192));
                ao.x += v.x; ao.y += v.y; ao.z += v.z; ao.w += v.w;
            }
            float4 hn;
            {
                float iv = sigf(ai.x + bi.x), fv = sigf(af.x + bf.x);
                float gv = tanhe(ag.x + bg4.x), ov = sigf(ao.x + bo.x);
                creg.x = fv * creg.x + iv * gv; hn.x = ov * tanhe(creg.x);
                iv = sigf(ai.y + bi.y); fv = sigf(af.y + bf.y);
                gv = tanhe(ag.y + bg4.y); ov = sigf(ao.y + bo.y);
                creg.y = fv * creg.y + iv * gv; hn.y = ov * tanhe(creg.y);
                iv = sigf(ai.z + bi.z); fv = sigf(af.z + bf.z);
                gv = tanhe(ag.z + bg4.z); ov = sigf(ao.z + bo.z);
                creg.z = fv * creg.z + iv * gv; hn.z = ov * tanhe(creg.z);
                iv = sigf(ai.w + bi.w); fv = sigf(af.w + bf.w);
                gv = tanhe(ag.w + bg4.w); ov = sigf(ao.w + bo.w);
                creg.w = fv * creg.w + iv * gv; hn.w = ov * tanhe(creg.w);
            }
            hlast = hn;
            const int cc = ct3 * 128 + c4;
            __stcg(reinterpret_cast<float4*>(&g_hbuf[pn][bb * 512 + cc]), hn);
            *reinterpret_cast<float4*>(&out[bb * (512 * 512) + t * 512 + cc]) = hn;
        }
        __syncthreads();
        if (tid == 0) {
            __threadfence();
            redrel(&g_hcnt[ct3 * 64]);
        }
    }

    if (tid < 64) {
        const int bb = b0 + boff;
        const int cc = ct3 * 128 + c4;
        *reinterpret_cast<float4*>(&out[16777216 + bb * 512 + cc]) = hlast;
        *reinterpret_cast<float4*>(&out[16777216 + 32768 + bb * 512 + cc]) = creg;
    }
}

extern "C" void kernel_launch(void* const* d_in, const int* in_sizes, int n_in,
                              void* d_out, int out_size) {
    const float* x      = (const float*)d_in[0];
    const float* Ws     = (const float*)d_in[1];
    const float* Us     = (const float*)d_in[2];
    const float* biases = (const float*)d_in[3];
    const float* Wc     = (const float*)d_in[4];
    const float* bc     = (const float*)d_in[5];
    float* out = (float*)d_out;
    (void)in_sizes; (void)n_in; (void)out_size;

    zero_kernel<<<32, 256>>>();
    cudaFuncSetAttribute(slstm_kernel, cudaFuncAttributeMaxDynamicSharedMemorySize,
                         SMEM_BYTES);
    slstm_kernel<<<NCTA, NTHR, SMEM_BYTES>>>(x, Ws, Us, biases, Wc, bc, out);
}